// round 1
// baseline (speedup 1.0000x reference)
#include <cuda_runtime.h>
#include <math.h>

#define B_ 256
#define T_ 128
#define D_ 256
#define H_ 512
#define BT_ (B_*T_)
#define G4H_ (4*H_)
#define XHAT_OFF (T_*B_*2)   /* 65536 floats: outs come first in d_out */

// Scratch (device globals: allocation-free rule)
__device__ float g_gammaH[(size_t)T_*B_*H_];      //  67 MB, [T,B,H]
__device__ float g_preGates[(size_t)T_*B_*G4H_];  // 268 MB, [T,B,4H]
__device__ float g_h[B_*H_];
__device__ float g_c[B_*H_];

typedef unsigned long long u64;
union F2U { u64 u; float2 f; };

__device__ __forceinline__ u64 ffma2(u64 a, u64 b, u64 c) {
    u64 d;
    asm("fma.rn.f32x2 %0, %1, %2, %3;" : "=l"(d) : "l"(a), "l"(b), "l"(c));
    return d;
}
__device__ __forceinline__ u64 dup2(float x) {
    F2U t; t.f.x = x; t.f.y = x; return t.u;
}
__device__ __forceinline__ float sigm(float x) { return 1.f/(1.f+expf(-x)); }

// ---------------------------------------------------------------------------
// Tiled GEMM mainloop using packed f32x2 FMAs.
//   Tile: (MM*16) x 128, K-chunk 16, 256 threads, micro-tile MM x 8 per thread.
//   BTN=false: B is [K,N] row-major (ldb = N-stride)
//   BTN=true : B is [N,K] row-major (ldb = K-stride)   ("@ W^T" gemms)
//   APROD    : A element = A[.] * Ascale[.]            (gamma_h ⊙ h)
// ---------------------------------------------------------------------------
template<int MM, bool BTN, bool APROD>
__device__ __forceinline__ void gemm_tile(
    const float* __restrict__ A, const float* __restrict__ Ascale, int lda,
    const float* __restrict__ Bg, int ldb,
    int m0, int n0, int k0, int klen,
    u64 acc[MM][4])
{
    constexpr int MT = MM*16;
    __shared__ u64   Asm[16][MT];    // A values duplicated into (x,x) pairs
    __shared__ float Bsm[16][128];
    const int tid = threadIdx.x;
    const int ty  = tid >> 4, tx = tid & 15;
    const int mb  = ty*MM,    nb = tx*8;

    for (int kc = k0; kc < k0 + klen; kc += 16) {
        // --- stage A tile (MT x 16) ---
        for (int i = tid; i < MT*4; i += 256) {
            int mm = i >> 2;
            int kk = (i & 3) << 2;
            float4 av = *reinterpret_cast<const float4*>(&A[(size_t)(m0+mm)*lda + kc+kk]);
            if constexpr (APROD) {
                float4 sv = *reinterpret_cast<const float4*>(&Ascale[(size_t)(m0+mm)*lda + kc+kk]);
                av.x *= sv.x; av.y *= sv.y; av.z *= sv.z; av.w *= sv.w;
            }
            Asm[kk+0][mm] = dup2(av.x); Asm[kk+1][mm] = dup2(av.y);
            Asm[kk+2][mm] = dup2(av.z); Asm[kk+3][mm] = dup2(av.w);
        }
        // --- stage B tile (16 x 128) ---
        if constexpr (!BTN) {
            #pragma unroll
            for (int i = 0; i < 2; i++) {
                int idx = tid + i*256;
                int kk  = idx >> 5;
                int nn  = (idx & 31) << 2;
                *reinterpret_cast<float4*>(&Bsm[kk][nn]) =
                    *reinterpret_cast<const float4*>(&Bg[(size_t)(kc+kk)*ldb + n0+nn]);
            }
        } else {
            #pragma unroll
            for (int i = 0; i < 2; i++) {
                int idx = tid + i*256;
                int nn  = idx >> 2;
                int kk  = (idx & 3) << 2;
                float4 bv = *reinterpret_cast<const float4*>(&Bg[(size_t)(n0+nn)*ldb + kc+kk]);
                Bsm[kk+0][nn] = bv.x; Bsm[kk+1][nn] = bv.y;
                Bsm[kk+2][nn] = bv.z; Bsm[kk+3][nn] = bv.w;
            }
        }
        __syncthreads();
        // --- compute ---
        #pragma unroll
        for (int kk = 0; kk < 16; kk++) {
            u64 b0 = *reinterpret_cast<const u64*>(&Bsm[kk][nb+0]);
            u64 b1 = *reinterpret_cast<const u64*>(&Bsm[kk][nb+2]);
            u64 b2 = *reinterpret_cast<const u64*>(&Bsm[kk][nb+4]);
            u64 b3 = *reinterpret_cast<const u64*>(&Bsm[kk][nb+6]);
            #pragma unroll
            for (int i = 0; i < MM; i++) {
                u64 a = Asm[kk][mb+i];
                acc[i][0] = ffma2(a, b0, acc[i][0]);
                acc[i][1] = ffma2(a, b1, acc[i][1]);
                acc[i][2] = ffma2(a, b2, acc[i][2]);
                acc[i][3] = ffma2(a, b3, acc[i][3]);
            }
        }
        __syncthreads();
    }
}

// ---------------------------------------------------------------------------
// init h, c from broadcast h0, c0
// ---------------------------------------------------------------------------
__global__ void __launch_bounds__(H_) k_init(const float* __restrict__ h0,
                                             const float* __restrict__ c0)
{
    int b = blockIdx.x, h = threadIdx.x;
    g_h[b*H_ + h] = h0[h];
    g_c[b*H_ + h] = c0[h];
}

// ---------------------------------------------------------------------------
// G1: gamma_x = exp(-relu(dt@w_gx + h_gx)); fused imputation -> xs -> xhats out
// grid (BT/64, D/128)
// ---------------------------------------------------------------------------
__global__ void __launch_bounds__(256) k_g1(
    const float* __restrict__ dt,   const float* __restrict__ wgx,
    const float* __restrict__ hgx,  const float* __restrict__ x,
    const float* __restrict__ mask, const float* __restrict__ xmean,
    float* __restrict__ out)
{
    u64 acc[4][4] = {};
    int m0 = blockIdx.x*64, n0 = blockIdx.y*128;
    gemm_tile<4,false,false>(dt, nullptr, D_, wgx, D_, m0, n0, 0, D_, acc);
    int ty = threadIdx.x >> 4, tx = threadIdx.x & 15;
    #pragma unroll
    for (int i = 0; i < 4; i++) {
        int row = m0 + ty*4 + i;      // row = b*T + t
        int b = row >> 7;
        int t = row & (T_-1);
        #pragma unroll
        for (int j = 0; j < 4; j++) {
            F2U v; v.u = acc[i][j];
            int d0 = n0 + tx*8 + 2*j;
            float vals[2] = { v.f.x, v.f.y };
            #pragma unroll
            for (int q = 0; q < 2; q++) {
                int d = d0 + q;
                float gamma = expf(-fmaxf(vals[q] + hgx[d], 0.f));
                float mv = mask[(size_t)row*D_ + d];
                float xt = x[(size_t)row*D_ + d];
                float xm = xmean[d];
                float imp = (t == 0) ? xm
                          : fmaf(gamma, x[(size_t)(row-1)*D_ + d], (1.f-gamma)*xm);
                out[XHAT_OFF + ((size_t)t*B_ + b)*D_ + d] = xt*mv + (1.f-mv)*imp;
            }
        }
    }
}

// ---------------------------------------------------------------------------
// G2: gamma_h = exp(-relu(dt@w_gh + h_gh))  -> g_gammaH [T,B,H]
// grid (BT/64, H/128)
// ---------------------------------------------------------------------------
__global__ void __launch_bounds__(256) k_g2(
    const float* __restrict__ dt, const float* __restrict__ wgh,
    const float* __restrict__ hgh)
{
    u64 acc[4][4] = {};
    int m0 = blockIdx.x*64, n0 = blockIdx.y*128;
    gemm_tile<4,false,false>(dt, nullptr, D_, wgh, H_, m0, n0, 0, D_, acc);
    int ty = threadIdx.x >> 4, tx = threadIdx.x & 15;
    #pragma unroll
    for (int i = 0; i < 4; i++) {
        int row = m0 + ty*4 + i;
        int b = row >> 7;
        int t = row & (T_-1);
        #pragma unroll
        for (int j = 0; j < 4; j++) {
            F2U v; v.u = acc[i][j];
            int n0j = n0 + tx*8 + 2*j;
            g_gammaH[((size_t)t*B_ + b)*H_ + n0j + 0] = expf(-fmaxf(v.f.x + hgh[n0j+0], 0.f));
            g_gammaH[((size_t)t*B_ + b)*H_ + n0j + 1] = expf(-fmaxf(v.f.y + hgh[n0j+1], 0.f));
        }
    }
}

// ---------------------------------------------------------------------------
// G3: pre_gates = xs @ W_ih^T + b_ih + b_hh   -> g_preGates [T,B,4H]
// xs read from d_out xhat region ([T*B, D]); row index is already t*B+b.
// grid (BT/64, 4H/128)
// ---------------------------------------------------------------------------
__global__ void __launch_bounds__(256) k_g3(
    const float* __restrict__ xsrc, const float* __restrict__ Wih,
    const float* __restrict__ bih,  const float* __restrict__ bhh)
{
    u64 acc[4][4] = {};
    int m0 = blockIdx.x*64, n0 = blockIdx.y*128;
    gemm_tile<4,true,false>(xsrc, nullptr, D_, Wih, D_, m0, n0, 0, D_, acc);
    int ty = threadIdx.x >> 4, tx = threadIdx.x & 15;
    #pragma unroll
    for (int i = 0; i < 4; i++) {
        int row = m0 + ty*4 + i;    // row = t*B + b
        #pragma unroll
        for (int j = 0; j < 4; j++) {
            F2U v; v.u = acc[i][j];
            int n = n0 + tx*8 + 2*j;
            g_preGates[(size_t)row*G4H_ + n + 0] = v.f.x + bih[n+0] + bhh[n+0];
            g_preGates[(size_t)row*G4H_ + n + 1] = v.f.y + bih[n+1] + bhh[n+1];
        }
    }
}

// ---------------------------------------------------------------------------
// Recurrent GEMM step t: gates += (gamma_h[t] ⊙ h) @ W_hh^T  (in-place on
// the pre_gates slab for step t).  M=256, N=2048, K=512. grid (8,16), no
// split-K -> each output owned by one thread (no atomics, deterministic).
// ---------------------------------------------------------------------------
__global__ void __launch_bounds__(256) k_rec(const float* __restrict__ Whh, int t)
{
    u64 acc[2][4] = {};
    int m0 = blockIdx.x*32, n0 = blockIdx.y*128;
    const float* gh = g_gammaH + (size_t)t*B_*H_;
    gemm_tile<2,true,true>(g_h, gh, H_, Whh, H_, m0, n0, 0, H_, acc);
    float* gates = g_preGates + (size_t)t*B_*G4H_;
    int ty = threadIdx.x >> 4, tx = threadIdx.x & 15;
    #pragma unroll
    for (int i = 0; i < 2; i++) {
        int bb = m0 + ty*2 + i;
        #pragma unroll
        for (int j = 0; j < 4; j++) {
            F2U v; v.u = acc[i][j];
            int n = n0 + tx*8 + 2*j;
            gates[(size_t)bb*G4H_ + n + 0] += v.f.x;
            gates[(size_t)bb*G4H_ + n + 1] += v.f.y;
        }
    }
}

// ---------------------------------------------------------------------------
// Cell + time-gate + output head, step t.  grid = B, block = H.
// ---------------------------------------------------------------------------
__global__ void __launch_bounds__(H_) k_cell(
    const float* __restrict__ tp, const float* __restrict__ wt,
    const float* __restrict__ ht, const float* __restrict__ W1,
    const float* __restrict__ b1, const float* __restrict__ W2,
    const float* __restrict__ b2, float* __restrict__ out, int t)
{
    __shared__ float h1s[H_];
    __shared__ float W1s[H_*10];
    __shared__ float zs[10];
    int b = blockIdx.x, h = threadIdx.x;

    for (int i = h; i < H_*10; i += H_) W1s[i] = W1[i];

    const float* gates = g_preGates + ((size_t)t*B_ + b)*G4H_;
    float gI = gates[h], gF = gates[H_+h], gG = gates[2*H_+h], gO = gates[3*H_+h];
    float gh = g_gammaH[((size_t)t*B_ + b)*H_ + h];
    float cd = g_c[b*H_ + h] * gh;
    float c1 = sigm(gF)*cd + sigm(gI)*tanhf(gG);
    float h1 = sigm(gO)*tanhf(c1);
    float gt = sigm(tp[b*T_ + t]*wt[h] + ht[h]);
    h1 *= gt; c1 *= gt;
    g_h[b*H_ + h] = h1;
    g_c[b*H_ + h] = c1;
    h1s[h] = h1;
    __syncthreads();

    int w = h >> 5, l = h & 31;
    if (w < 10) {
        float s = 0.f;
        for (int k = l; k < H_; k += 32) s = fmaf(h1s[k], W1s[k*10 + w], s);
        #pragma unroll
        for (int off = 16; off; off >>= 1) s += __shfl_xor_sync(0xffffffffu, s, off);
        if (l == 0) zs[w] = sigm(s + b1[w]);
    }
    __syncthreads();

    if (h == 0) {
        float z0 = b2[0], z1 = b2[1];
        #pragma unroll
        for (int j = 0; j < 10; j++) {
            z0 = fmaf(zs[j], W2[j*2+0], z0);
            z1 = fmaf(zs[j], W2[j*2+1], z1);
        }
        z0 = sigm(z0); z1 = sigm(z1);
        float m  = fmaxf(z0, z1);
        float e0 = expf(z0 - m), e1 = expf(z1 - m);
        float inv = 1.f/(e0 + e1);
        out[((size_t)t*B_ + b)*2 + 0] = e0*inv;
        out[((size_t)t*B_ + b)*2 + 1] = e1*inv;
    }
}

// ---------------------------------------------------------------------------
extern "C" void kernel_launch(void* const* d_in, const int* in_sizes, int n_in,
                              void* d_out, int out_size)
{
    const float* x     = (const float*)d_in[0];
    const float* dt    = (const float*)d_in[1];
    const float* mask  = (const float*)d_in[2];
    const float* tp    = (const float*)d_in[3];
    const float* xmean = (const float*)d_in[4];
    const float* h0    = (const float*)d_in[5];
    const float* c0    = (const float*)d_in[6];
    const float* wgx   = (const float*)d_in[7];
    const float* hgx   = (const float*)d_in[8];
    const float* wgh   = (const float*)d_in[9];
    const float* hgh   = (const float*)d_in[10];
    const float* wt    = (const float*)d_in[11];
    const float* ht    = (const float*)d_in[12];
    const float* Wih   = (const float*)d_in[13];
    const float* Whh   = (const float*)d_in[14];
    const float* bih   = (const float*)d_in[15];
    const float* bhh   = (const float*)d_in[16];
    const float* W1    = (const float*)d_in[17];
    const float* b1    = (const float*)d_in[18];
    const float* W2    = (const float*)d_in[19];
    const float* b2    = (const float*)d_in[20];
    float* out = (float*)d_out;

    k_init<<<B_, H_>>>(h0, c0);
    k_g1<<<dim3(BT_/64, D_/128),   256>>>(dt, wgx, hgx, x, mask, xmean, out);
    k_g2<<<dim3(BT_/64, H_/128),   256>>>(dt, wgh, hgh);
    k_g3<<<dim3(BT_/64, G4H_/128), 256>>>(out + XHAT_OFF, Wih, bih, bhh);

    for (int t = 0; t < T_; t++) {
        k_rec<<<dim3(B_/32, G4H_/128), 256>>>(Whh, t);
        k_cell<<<B_, H_>>>(tp, wt, ht, W1, b1, W2, b2, out, t);
    }
}

// round 2
// speedup vs baseline: 1.1792x; 1.1792x over previous
#include <cuda_runtime.h>
#include <math.h>

#define B_ 256
#define T_ 128
#define D_ 256
#define H_ 512
#define BT_ (B_*T_)
#define G4H_ (4*H_)
#define XHAT_OFF (T_*B_*2)   /* 65536 floats: outs come first in d_out */

// Scratch (device globals: allocation-free rule)
__device__ float g_gammaH[(size_t)T_*B_*H_];      //  67 MB, [T,B,H]
__device__ float g_preGates[(size_t)T_*B_*G4H_];  // 268 MB, [T,B,4H]
__device__ float g_h[B_*H_];
__device__ float g_c[B_*H_];

typedef unsigned long long u64;
union F2U { u64 u; float2 f; };

__device__ __forceinline__ u64 ffma2(u64 a, u64 b, u64 c) {
    u64 d;
    asm("fma.rn.f32x2 %0, %1, %2, %3;" : "=l"(d) : "l"(a), "l"(b), "l"(c));
    return d;
}
__device__ __forceinline__ u64 dup2(float x) {
    F2U t; t.f.x = x; t.f.y = x; return t.u;
}
__device__ __forceinline__ float sigm(float x) { return 1.f/(1.f+expf(-x)); }

// ---------------------------------------------------------------------------
// Double-buffered tiled GEMM mainloop using packed f32x2 FMAs.
//   Tile: (MM*16) x 128, K-chunk 16, 256 threads, micro-tile MM x 8 per thread.
//   BTN=false: B is [K,N] row-major.  BTN=true: B is [N,K] row-major (@W^T).
//   APROD: A element scaled by Ascale elementwise (gamma_h ⊙ h).
//   Pipeline: LDG(next) -> compute(cur smem) -> STS(next buf) -> bar.
// ---------------------------------------------------------------------------
template<int MM, bool BTN, bool APROD>
__device__ __forceinline__ void gemm_db(
    const float* __restrict__ A, const float* __restrict__ As, int lda,
    const float* __restrict__ Bg, int ldb,
    int m0, int n0, int K,
    u64 acc[MM][4])
{
    constexpr int MT = MM*16;
    constexpr int NA = (MT*4 + 255)/256;   // float4 A loads per thread
    __shared__ u64 Asm[2][16][MT];         // A dup-pairs, [k][m]
    __shared__ u64 Bsm[2][16][64];         // B as u64 pairs, [k][n/2]

    const int tid = threadIdx.x;
    const int tx  = tid & 15, ty = tid >> 4;
    const int mb  = ty*MM;
    const int C   = K >> 4;

    float4 aP[NA], sP[NA], bP[2];

    auto ldA = [&](int c) {
        int kc = c << 4;
        #pragma unroll
        for (int l = 0; l < NA; l++) {
            int idx = tid + l*256;
            if (MT*4 >= 256*(l+1) || idx < MT*4) {
                int m = idx >> 2, k4 = (idx & 3) << 2;
                aP[l] = *(const float4*)&A[(size_t)(m0+m)*lda + kc + k4];
                if (APROD)
                    sP[l] = *(const float4*)&As[(size_t)(m0+m)*lda + kc + k4];
            }
        }
    };
    auto stA = [&](int buf) {
        #pragma unroll
        for (int l = 0; l < NA; l++) {
            int idx = tid + l*256;
            if (MT*4 >= 256*(l+1) || idx < MT*4) {
                int m = idx >> 2, k = (idx & 3) << 2;
                float4 v = aP[l];
                if (APROD) {
                    float4 s = sP[l];
                    v.x *= s.x; v.y *= s.y; v.z *= s.z; v.w *= s.w;
                }
                Asm[buf][k+0][m] = dup2(v.x); Asm[buf][k+1][m] = dup2(v.y);
                Asm[buf][k+2][m] = dup2(v.z); Asm[buf][k+3][m] = dup2(v.w);
            }
        }
    };
    auto ldB = [&](int c) {
        int kc = c << 4;
        #pragma unroll
        for (int l = 0; l < 2; l++) {
            int idx = tid + l*256;
            if (!BTN) {
                int kk = idx >> 5, n4 = (idx & 31) << 2;
                bP[l] = *(const float4*)&Bg[(size_t)(kc+kk)*ldb + n0 + n4];
            } else {
                int n = idx >> 2, k4 = (idx & 3) << 2;
                bP[l] = *(const float4*)&Bg[(size_t)(n0+n)*ldb + kc + k4];
            }
        }
    };
    auto stB = [&](int buf) {
        #pragma unroll
        for (int l = 0; l < 2; l++) {
            int idx = tid + l*256;
            if (!BTN) {
                int kk = idx >> 5, n4 = (idx & 31) << 2;
                *(float4*)&((float*)Bsm[buf][kk])[n4] = bP[l];
            } else {
                int n = idx >> 2, k = (idx & 3) << 2;
                ((float*)Bsm[buf][k+0])[n] = bP[l].x;
                ((float*)Bsm[buf][k+1])[n] = bP[l].y;
                ((float*)Bsm[buf][k+2])[n] = bP[l].z;
                ((float*)Bsm[buf][k+3])[n] = bP[l].w;
            }
        }
    };
    auto comp = [&](int buf) {
        #pragma unroll
        for (int kk = 0; kk < 16; kk++) {
            const u64* br = &Bsm[buf][kk][tx*4];
            u64 b0 = br[0], b1 = br[1], b2 = br[2], b3 = br[3];
            const u64* ar = &Asm[buf][kk][mb];
            #pragma unroll
            for (int i = 0; i < MM; i++) {
                u64 a = ar[i];
                acc[i][0] = ffma2(a, b0, acc[i][0]);
                acc[i][1] = ffma2(a, b1, acc[i][1]);
                acc[i][2] = ffma2(a, b2, acc[i][2]);
                acc[i][3] = ffma2(a, b3, acc[i][3]);
            }
        }
    };

    ldA(0); ldB(0); stA(0); stB(0);
    __syncthreads();
    for (int c = 0; c < C; c++) {
        int cur = c & 1;
        if (c + 1 < C) { ldA(c+1); ldB(c+1); }
        comp(cur);
        if (c + 1 < C) { stA(cur^1); stB(cur^1); __syncthreads(); }
    }
}

// ---------------------------------------------------------------------------
// init h, c from broadcast h0, c0
// ---------------------------------------------------------------------------
__global__ void __launch_bounds__(H_) k_init(const float* __restrict__ h0,
                                             const float* __restrict__ c0)
{
    int b = blockIdx.x, h = threadIdx.x;
    g_h[b*H_ + h] = h0[h];
    g_c[b*H_ + h] = c0[h];
}

// ---------------------------------------------------------------------------
// G1: gamma_x = exp(-relu(dt@w_gx + h_gx)); fused imputation -> xs -> xhats
// grid (BT/128, D/128)
// ---------------------------------------------------------------------------
__global__ void __launch_bounds__(256) k_g1(
    const float* __restrict__ dt,   const float* __restrict__ wgx,
    const float* __restrict__ hgx,  const float* __restrict__ x,
    const float* __restrict__ mask, const float* __restrict__ xmean,
    float* __restrict__ out)
{
    u64 acc[8][4] = {};
    int m0 = blockIdx.x*128, n0 = blockIdx.y*128;
    gemm_db<8,false,false>(dt, nullptr, D_, wgx, D_, m0, n0, D_, acc);
    int tx = threadIdx.x & 15, ty = threadIdx.x >> 4;
    #pragma unroll
    for (int i = 0; i < 8; i++) {
        int row = m0 + ty*8 + i;      // row = b*T + t
        int b = row >> 7;
        int t = row & (T_-1);
        #pragma unroll
        for (int j = 0; j < 4; j++) {
            F2U v; v.u = acc[i][j];
            int d0 = n0 + tx*8 + 2*j;
            float vals[2] = { v.f.x, v.f.y };
            #pragma unroll
            for (int q = 0; q < 2; q++) {
                int d = d0 + q;
                float gamma = expf(-fmaxf(vals[q] + hgx[d], 0.f));
                float mv = mask[(size_t)row*D_ + d];
                float xt = x[(size_t)row*D_ + d];
                float xm = xmean[d];
                float imp = (t == 0) ? xm
                          : fmaf(gamma, x[(size_t)(row-1)*D_ + d], (1.f-gamma)*xm);
                out[XHAT_OFF + ((size_t)t*B_ + b)*D_ + d] = xt*mv + (1.f-mv)*imp;
            }
        }
    }
}

// ---------------------------------------------------------------------------
// G2: gamma_h = exp(-relu(dt@w_gh + h_gh)) -> g_gammaH [T,B,H]
// grid (BT/128, H/128)
// ---------------------------------------------------------------------------
__global__ void __launch_bounds__(256) k_g2(
    const float* __restrict__ dt, const float* __restrict__ wgh,
    const float* __restrict__ hgh)
{
    u64 acc[8][4] = {};
    int m0 = blockIdx.x*128, n0 = blockIdx.y*128;
    gemm_db<8,false,false>(dt, nullptr, D_, wgh, H_, m0, n0, D_, acc);
    int tx = threadIdx.x & 15, ty = threadIdx.x >> 4;
    #pragma unroll
    for (int i = 0; i < 8; i++) {
        int row = m0 + ty*8 + i;
        int b = row >> 7;
        int t = row & (T_-1);
        #pragma unroll
        for (int j = 0; j < 4; j++) {
            F2U v; v.u = acc[i][j];
            int n = n0 + tx*8 + 2*j;
            g_gammaH[((size_t)t*B_ + b)*H_ + n + 0] = expf(-fmaxf(v.f.x + hgh[n+0], 0.f));
            g_gammaH[((size_t)t*B_ + b)*H_ + n + 1] = expf(-fmaxf(v.f.y + hgh[n+1], 0.f));
        }
    }
}

// ---------------------------------------------------------------------------
// G3: pre_gates = xs @ W_ih^T + b_ih + b_hh -> g_preGates [T,B,4H]
// grid (BT/128, 4H/128)
// ---------------------------------------------------------------------------
__global__ void __launch_bounds__(256) k_g3(
    const float* __restrict__ xsrc, const float* __restrict__ Wih,
    const float* __restrict__ bih,  const float* __restrict__ bhh)
{
    u64 acc[8][4] = {};
    int m0 = blockIdx.x*128, n0 = blockIdx.y*128;
    gemm_db<8,true,false>(xsrc, nullptr, D_, Wih, D_, m0, n0, D_, acc);
    int tx = threadIdx.x & 15, ty = threadIdx.x >> 4;
    #pragma unroll
    for (int i = 0; i < 8; i++) {
        int row = m0 + ty*8 + i;    // row = t*B + b
        #pragma unroll
        for (int j = 0; j < 4; j++) {
            F2U v; v.u = acc[i][j];
            int n = n0 + tx*8 + 2*j;
            g_preGates[(size_t)row*G4H_ + n + 0] = v.f.x + bih[n+0] + bhh[n+0];
            g_preGates[(size_t)row*G4H_ + n + 1] = v.f.y + bih[n+1] + bhh[n+1];
        }
    }
}

// ---------------------------------------------------------------------------
// Recurrent GEMM step t: gates += (gamma_h[t] ⊙ h) @ W_hh^T  (in place).
// M=256, N=2048, K=512. grid (8,16) = 128 CTAs (one wave), no split-K.
// ---------------------------------------------------------------------------
__global__ void __launch_bounds__(256) k_rec(const float* __restrict__ Whh, int t)
{
    u64 acc[2][4] = {};
    int m0 = blockIdx.x*32, n0 = blockIdx.y*128;
    const float* gh = g_gammaH + (size_t)t*B_*H_;
    gemm_db<2,true,true>(g_h, gh, H_, Whh, H_, m0, n0, H_, acc);
    float* gates = g_preGates + (size_t)t*B_*G4H_;
    int tx = threadIdx.x & 15, ty = threadIdx.x >> 4;
    #pragma unroll
    for (int i = 0; i < 2; i++) {
        int bb = m0 + ty*2 + i;
        #pragma unroll
        for (int j = 0; j < 4; j++) {
            F2U v; v.u = acc[i][j];
            int n = n0 + tx*8 + 2*j;
            gates[(size_t)bb*G4H_ + n + 0] += v.f.x;
            gates[(size_t)bb*G4H_ + n + 1] += v.f.y;
        }
    }
}

// ---------------------------------------------------------------------------
// Cell + time-gate + output head, step t.  grid = B, block = H.
// ---------------------------------------------------------------------------
__global__ void __launch_bounds__(H_) k_cell(
    const float* __restrict__ tp, const float* __restrict__ wt,
    const float* __restrict__ ht, const float* __restrict__ W1,
    const float* __restrict__ b1, const float* __restrict__ W2,
    const float* __restrict__ b2, float* __restrict__ out, int t)
{
    __shared__ float h1s[H_];
    __shared__ float W1s[H_*10];
    __shared__ float zs[10];
    int b = blockIdx.x, h = threadIdx.x;

    for (int i = h; i < H_*10; i += H_) W1s[i] = W1[i];

    const float* gates = g_preGates + ((size_t)t*B_ + b)*G4H_;
    float gI = gates[h], gF = gates[H_+h], gG = gates[2*H_+h], gO = gates[3*H_+h];
    float gh = g_gammaH[((size_t)t*B_ + b)*H_ + h];
    float cd = g_c[b*H_ + h] * gh;
    float c1 = sigm(gF)*cd + sigm(gI)*tanhf(gG);
    float h1 = sigm(gO)*tanhf(c1);
    float gt = sigm(tp[b*T_ + t]*wt[h] + ht[h]);
    h1 *= gt; c1 *= gt;
    g_h[b*H_ + h] = h1;
    g_c[b*H_ + h] = c1;
    h1s[h] = h1;
    __syncthreads();

    int w = h >> 5, l = h & 31;
    if (w < 10) {
        float s = 0.f;
        for (int k = l; k < H_; k += 32) s = fmaf(h1s[k], W1s[k*10 + w], s);
        #pragma unroll
        for (int off = 16; off; off >>= 1) s += __shfl_xor_sync(0xffffffffu, s, off);
        if (l == 0) zs[w] = sigm(s + b1[w]);
    }
    __syncthreads();

    if (h == 0) {
        float z0 = b2[0], z1 = b2[1];
        #pragma unroll
        for (int j = 0; j < 10; j++) {
            z0 = fmaf(zs[j], W2[j*2+0], z0);
            z1 = fmaf(zs[j], W2[j*2+1], z1);
        }
        z0 = sigm(z0); z1 = sigm(z1);
        float m  = fmaxf(z0, z1);
        float e0 = expf(z0 - m), e1 = expf(z1 - m);
        float inv = 1.f/(e0 + e1);
        out[((size_t)t*B_ + b)*2 + 0] = e0*inv;
        out[((size_t)t*B_ + b)*2 + 1] = e1*inv;
    }
}

// ---------------------------------------------------------------------------
extern "C" void kernel_launch(void* const* d_in, const int* in_sizes, int n_in,
                              void* d_out, int out_size)
{
    const float* x     = (const float*)d_in[0];
    const float* dt    = (const float*)d_in[1];
    const float* mask  = (const float*)d_in[2];
    const float* tp    = (const float*)d_in[3];
    const float* xmean = (const float*)d_in[4];
    const float* h0    = (const float*)d_in[5];
    const float* c0    = (const float*)d_in[6];
    const float* wgx   = (const float*)d_in[7];
    const float* hgx   = (const float*)d_in[8];
    const float* wgh   = (const float*)d_in[9];
    const float* hgh   = (const float*)d_in[10];
    const float* wt    = (const float*)d_in[11];
    const float* ht    = (const float*)d_in[12];
    const float* Wih   = (const float*)d_in[13];
    const float* Whh   = (const float*)d_in[14];
    const float* bih   = (const float*)d_in[15];
    const float* bhh   = (const float*)d_in[16];
    const float* W1    = (const float*)d_in[17];
    const float* b1    = (const float*)d_in[18];
    const float* W2    = (const float*)d_in[19];
    const float* b2    = (const float*)d_in[20];
    float* out = (float*)d_out;

    k_init<<<B_, H_>>>(h0, c0);
    k_g1<<<dim3(BT_/128, D_/128),   256>>>(dt, wgx, hgx, x, mask, xmean, out);
    k_g2<<<dim3(BT_/128, H_/128),   256>>>(dt, wgh, hgh);
    k_g3<<<dim3(BT_/128, G4H_/128), 256>>>(out + XHAT_OFF, Wih, bih, bhh);

    for (int t = 0; t < T_; t++) {
        k_rec<<<dim3(B_/32, G4H_/128), 256>>>(Whh, t);
        k_cell<<<B_, H_>>>(tp, wt, ht, W1, b1, W2, b2, out, t);
    }
}

// round 3
// speedup vs baseline: 2.0907x; 1.7730x over previous
#include <cuda_runtime.h>
#include <math.h>

#define B_ 256
#define T_ 128
#define D_ 256
#define H_ 512
#define BT_ (B_*T_)
#define G4H_ 2048
#define XHAT_OFF (T_*B_*2)   /* outs [T,B,2] first, then xhats [T,B,D] */
#define LDK 260              /* smem row: 256 floats + 4 pad (1040B, 16B aligned) */
#define NCTA_LOOP 128

// ---- device scratch (allocation-free rule) ----
__device__ float g_gammaH[(size_t)T_*B_*H_];      // [T,B,H]
__device__ float g_preGates[(size_t)T_*B_*G4H_];  // [T,B,4H]
__device__ float g_part[2][B_][G4H_];             // split-K partials
__device__ float g_hbuf[2][B_][H_];               // double-buffered h
__device__ float g_wT[(D_+H_)*D_];                // wgxT [256,256] then wghT [512,256]
__device__ unsigned g_barC, g_barS;               // grid barrier (self-restoring)

typedef unsigned long long u64;
union F2U { u64 u; float2 f; };

__device__ __forceinline__ u64 ffma2(u64 a, u64 b, u64 c) {
    u64 d; asm("fma.rn.f32x2 %0,%1,%2,%3;" : "=l"(d) : "l"(a), "l"(b), "l"(c)); return d;
}
__device__ __forceinline__ float sigm(float x){ return 1.f/(1.f+expf(-x)); }
__device__ __forceinline__ float ldcg(const float* p){
    float v; asm volatile("ld.global.cg.f32 %0,[%1];" : "=f"(v) : "l"(p)); return v;
}
__device__ __forceinline__ float4 ldcg4(const float* p){
    float4 v; asm volatile("ld.global.cg.v4.f32 {%0,%1,%2,%3},[%4];"
        : "=f"(v.x),"=f"(v.y),"=f"(v.z),"=f"(v.w) : "l"(p)); return v;
}
__device__ __forceinline__ void stcg(float* p, float v){
    asm volatile("st.global.cg.f32 [%0],%1;" :: "l"(p), "f"(v));
}

// ---------------------------------------------------------------------------
// Core 64x128xK256 mainloop, pair-over-K f32x2 FMAs. As:[64][LDK], Bs:[128][LDK].
// Thread (tx=tid&15 -> c=tx+16j, j<8 ; ty=tid>>4 -> m=ty+16i, i<4). acc[i][j].
// ---------------------------------------------------------------------------
__device__ __forceinline__ void mm64x128(const float* As, const float* Bs,
                                         u64 acc[4][8], int tx, int ty)
{
    #pragma unroll 2
    for (int kp = 0; kp < 128; kp++) {
        u64 a[4], w[8];
        #pragma unroll
        for (int i = 0; i < 4; i++) a[i] = *(const u64*)&As[(ty+16*i)*LDK + 2*kp];
        #pragma unroll
        for (int j = 0; j < 8; j++) w[j] = *(const u64*)&Bs[(tx+16*j)*LDK + 2*kp];
        #pragma unroll
        for (int i = 0; i < 4; i++)
            #pragma unroll
            for (int j = 0; j < 8; j++) acc[i][j] = ffma2(a[i], w[j], acc[i][j]);
    }
}

// direct copy gmem->smem, rows of 256 floats (from col0), row-major src
__device__ __forceinline__ void load_tile(float* dst, const float* src,
                                          int rows, int row0, int ld, int col0)
{
    for (int i = threadIdx.x; i < rows*64; i += 256) {
        int r = i >> 6, q = (i & 63) << 2;
        *(float4*)&dst[r*LDK + q] = *(const float4*)&src[(size_t)(row0+r)*ld + col0 + q];
    }
}

// ---------------------------------------------------------------------------
__global__ void __launch_bounds__(H_) k_init(const float* __restrict__ h0)
{
    g_hbuf[0][blockIdx.x][threadIdx.x] = h0[threadIdx.x];
}

// transpose w_gx [K,256] and w_gh [K,512] -> g_wT as [N,K]
__global__ void __launch_bounds__(256) k_tr(const float* __restrict__ wgx,
                                            const float* __restrict__ wgh)
{
    int blk = blockIdx.x, k = threadIdx.x;
    if (blk < 256) g_wT[blk*D_ + k] = wgx[k*D_ + blk];
    else { int n = blk - 256; g_wT[D_*D_ + n*D_ + k] = wgh[k*H_ + n]; }
}

// ---------------------------------------------------------------------------
// G1: gamma_x + imputation -> xhat.  grid (BT/64, 2)
// ---------------------------------------------------------------------------
__global__ void __launch_bounds__(256) k_g1(
    const float* __restrict__ dt,  const float* __restrict__ hgx,
    const float* __restrict__ x,   const float* __restrict__ mask,
    const float* __restrict__ xmean, float* __restrict__ out)
{
    extern __shared__ float sm[];
    float *As = sm, *Bs = sm + 64*LDK;
    int m0 = blockIdx.x*64, n0 = blockIdx.y*128;
    load_tile(As, dt, 64, m0, D_, 0);
    load_tile(Bs, g_wT, 128, n0, D_, 0);
    __syncthreads();
    int tx = threadIdx.x & 15, ty = threadIdx.x >> 4;
    u64 acc[4][8] = {};
    mm64x128(As, Bs, acc, tx, ty);
    #pragma unroll
    for (int i = 0; i < 4; i++) {
        int row = m0 + ty + 16*i;          // row = b*T + t
        int b = row >> 7, t = row & (T_-1);
        #pragma unroll
        for (int j = 0; j < 8; j++) {
            int d = n0 + tx + 16*j;
            F2U v; v.u = acc[i][j];
            float gamma = expf(-fmaxf(v.f.x + v.f.y + hgx[d], 0.f));
            float mv = mask[(size_t)row*D_ + d];
            float xt = x[(size_t)row*D_ + d];
            float xm = xmean[d];
            float imp = (t == 0) ? xm
                      : fmaf(gamma, x[(size_t)(row-1)*D_ + d], (1.f-gamma)*xm);
            out[XHAT_OFF + ((size_t)t*B_ + b)*D_ + d] = xt*mv + (1.f-mv)*imp;
        }
    }
}

// ---------------------------------------------------------------------------
// G2: gamma_h -> g_gammaH.  grid (BT/64, 4)
// ---------------------------------------------------------------------------
__global__ void __launch_bounds__(256) k_g2(
    const float* __restrict__ dt, const float* __restrict__ hgh)
{
    extern __shared__ float sm[];
    float *As = sm, *Bs = sm + 64*LDK;
    int m0 = blockIdx.x*64, n0 = blockIdx.y*128;
    load_tile(As, dt, 64, m0, D_, 0);
    load_tile(Bs, g_wT + D_*D_, 128, n0, D_, 0);
    __syncthreads();
    int tx = threadIdx.x & 15, ty = threadIdx.x >> 4;
    u64 acc[4][8] = {};
    mm64x128(As, Bs, acc, tx, ty);
    #pragma unroll
    for (int i = 0; i < 4; i++) {
        int row = m0 + ty + 16*i;
        int b = row >> 7, t = row & (T_-1);
        #pragma unroll
        for (int j = 0; j < 8; j++) {
            int u = n0 + tx + 16*j;
            F2U v; v.u = acc[i][j];
            g_gammaH[((size_t)t*B_ + b)*H_ + u] = expf(-fmaxf(v.f.x + v.f.y + hgh[u], 0.f));
        }
    }
}

// ---------------------------------------------------------------------------
// G3: pre_gates = xs @ W_ih^T + b_ih + b_hh.  grid (BT/64, 16)
// ---------------------------------------------------------------------------
__global__ void __launch_bounds__(256) k_g3(
    const float* __restrict__ xsrc, const float* __restrict__ Wih,
    const float* __restrict__ bih,  const float* __restrict__ bhh)
{
    extern __shared__ float sm[];
    float *As = sm, *Bs = sm + 64*LDK;
    int m0 = blockIdx.x*64, n0 = blockIdx.y*128;
    load_tile(As, xsrc, 64, m0, D_, 0);
    load_tile(Bs, Wih, 128, n0, D_, 0);
    __syncthreads();
    int tx = threadIdx.x & 15, ty = threadIdx.x >> 4;
    u64 acc[4][8] = {};
    mm64x128(As, Bs, acc, tx, ty);
    #pragma unroll
    for (int i = 0; i < 4; i++) {
        int row = m0 + ty + 16*i;          // row = t*B + b
        #pragma unroll
        for (int j = 0; j < 8; j++) {
            int c = n0 + tx + 16*j;
            F2U v; v.u = acc[i][j];
            g_preGates[(size_t)row*G4H_ + c] = v.f.x + v.f.y + bih[c] + bhh[c];
        }
    }
}

// ---------------------------------------------------------------------------
// self-restoring sense-reversing grid barrier (even call count per launch)
// ---------------------------------------------------------------------------
__device__ __forceinline__ void gridbar(unsigned &sense)
{
    __syncthreads();
    if (threadIdx.x == 0) {
        unsigned s = sense ^ 1;
        __threadfence();
        if (atomicAdd(&g_barC, 1u) == NCTA_LOOP-1) {
            atomicExch(&g_barC, 0u);
            __threadfence();
            atomicExch(&g_barS, s);
        } else {
            while (*(volatile unsigned*)&g_barS != s) __nanosleep(64);
        }
    }
    __syncthreads();
    sense ^= 1;
}

// ---------------------------------------------------------------------------
// Persistent recurrent kernel: 128 CTAs x 256 thr, all 128 steps.
// CTA = (kb, nb, mb): GEMM tile b[mb*64,+64) x c[nb*128,+128) x k[kb*256,+256).
// W_hh slice resident in smem for all steps. c-state in registers.
// ---------------------------------------------------------------------------
__global__ void __launch_bounds__(256) k_loop(
    const float* __restrict__ Whh, const float* __restrict__ c0,
    const float* __restrict__ tp,  const float* __restrict__ wt,
    const float* __restrict__ ht,  const float* __restrict__ W1,
    const float* __restrict__ b1,  const float* __restrict__ W2,
    const float* __restrict__ b2,  float* __restrict__ out)
{
    extern __shared__ float sm[];
    float *Wsm = sm;                    // 128*LDK
    float *ahs = sm + 128*LDK;          // 64*LDK
    float *h1s = sm + 192*LDK;          // 2*512
    float *zs  = h1s + 1024;            // 2*10

    const int tid = threadIdx.x, cta = blockIdx.x;
    const int kb = cta & 1, nb = (cta >> 1) & 15, mb = cta >> 5;
    const int b0 = mb*64, c0i = nb*128, k0 = kb*256;
    const int tx = tid & 15, ty = tid >> 4;
    unsigned sense = 0;

    // resident W_hh slice [128 c][256 k]
    load_tile(Wsm, Whh, 128, c0i, H_, k0);

    // cell ownership: 4 items/thread: u = tid + 256*(q&1), b = cta*2 + (q>>1)
    float c_reg[4], wtr[4], htr[4];
    int   ub[4], bb[4];
    #pragma unroll
    for (int q = 0; q < 4; q++) {
        ub[q] = tid + 256*(q & 1);
        bb[q] = cta*2 + (q >> 1);
        c_reg[q] = c0[ub[q]];
        wtr[q] = wt[ub[q]];
        htr[q] = ht[ub[q]];
    }
    __syncthreads();

    for (int t = 0; t < T_; t++) {
        const int p = t & 1;            // GEMM reads hbuf[p], cell writes hbuf[p^1]

        // ---- phase 1a: load h1s for head(t-1) + stage ah(t) ----
        if (t > 0)
            for (int i = tid; i < 1024; i += 256)
                h1s[i] = ldcg(&g_hbuf[p][cta*2 + (i >> 9)][i & 511]);
        for (int i = tid; i < 64*64; i += 256) {
            int r = i >> 6, q = (i & 63) << 2;
            int bg = b0 + r;
            float4 g = *(const float4*)&g_gammaH[((size_t)t*B_ + bg)*H_ + k0 + q];
            float4 h = ldcg4(&g_hbuf[p][bg][k0 + q]);
            g.x *= h.x; g.y *= h.y; g.z *= h.z; g.w *= h.w;
            *(float4*)&ahs[r*LDK + q] = g;
        }
        __syncthreads();

        // ---- head for step t-1 (reads h1s) ----
        if (t > 0) {
            int wid = tid >> 5, lane = tid & 31;
            for (int task = wid; task < 20; task += 8) {
                int hb = task / 10, z = task - hb*10;
                float s = 0.f;
                const float* hv = h1s + hb*512;
                for (int k = lane; k < H_; k += 32) s = fmaf(hv[k], W1[k*10 + z], s);
                #pragma unroll
                for (int off = 16; off; off >>= 1) s += __shfl_xor_sync(0xffffffffu, s, off);
                if (lane == 0) zs[hb*10 + z] = sigm(s + b1[z]);
            }
            __syncthreads();
            if (tid < 2) {
                float z0 = b2[0], z1 = b2[1];
                #pragma unroll
                for (int j = 0; j < 10; j++) {
                    z0 = fmaf(zs[tid*10 + j], W2[j*2 + 0], z0);
                    z1 = fmaf(zs[tid*10 + j], W2[j*2 + 1], z1);
                }
                z0 = sigm(z0); z1 = sigm(z1);
                float m = fmaxf(z0, z1);
                float e0 = expf(z0 - m), e1 = expf(z1 - m);
                float inv = 1.f/(e0 + e1);
                int bg = cta*2 + tid;
                out[((size_t)(t-1)*B_ + bg)*2 + 0] = e0*inv;
                out[((size_t)(t-1)*B_ + bg)*2 + 1] = e1*inv;
            }
        }

        // ---- phase 1b: GEMM slice ----
        u64 acc[4][8] = {};
        mm64x128(ahs, Wsm, acc, tx, ty);
        #pragma unroll
        for (int i = 0; i < 4; i++) {
            int bg = b0 + ty + 16*i;
            #pragma unroll
            for (int j = 0; j < 8; j++) {
                F2U v; v.u = acc[i][j];
                stcg(&g_part[kb][bg][c0i + tx + 16*j], v.f.x + v.f.y);
            }
        }
        gridbar(sense);

        // ---- phase 2: cell (register c-state) ----
        #pragma unroll
        for (int q = 0; q < 4; q++) {
            int u = ub[q], b = bb[q];
            const float* pre = &g_preGates[((size_t)t*B_ + b)*G4H_];
            float gi = pre[u]        + ldcg(&g_part[0][b][u])        + ldcg(&g_part[1][b][u]);
            float gf = pre[512 + u]  + ldcg(&g_part[0][b][512 + u])  + ldcg(&g_part[1][b][512 + u]);
            float gg = pre[1024 + u] + ldcg(&g_part[0][b][1024 + u]) + ldcg(&g_part[1][b][1024 + u]);
            float go = pre[1536 + u] + ldcg(&g_part[0][b][1536 + u]) + ldcg(&g_part[1][b][1536 + u]);
            float gh = g_gammaH[((size_t)t*B_ + b)*H_ + u];
            float c1 = sigm(gf)*(gh*c_reg[q]) + sigm(gi)*tanhf(gg);
            float h1 = sigm(go)*tanhf(c1);
            float gtv = sigm(tp[b*T_ + t]*wtr[q] + htr[q]);
            c_reg[q] = gtv*c1;
            stcg(&g_hbuf[p^1][b][u], gtv*h1);
        }
        gridbar(sense);
    }

    // ---- final head: step 127, h in hbuf[0] ----
    for (int i = tid; i < 1024; i += 256)
        h1s[i] = ldcg(&g_hbuf[0][cta*2 + (i >> 9)][i & 511]);
    __syncthreads();
    {
        int wid = tid >> 5, lane = tid & 31;
        for (int task = wid; task < 20; task += 8) {
            int hb = task / 10, z = task - hb*10;
            float s = 0.f;
            const float* hv = h1s + hb*512;
            for (int k = lane; k < H_; k += 32) s = fmaf(hv[k], W1[k*10 + z], s);
            #pragma unroll
            for (int off = 16; off; off >>= 1) s += __shfl_xor_sync(0xffffffffu, s, off);
            if (lane == 0) zs[hb*10 + z] = sigm(s + b1[z]);
        }
        __syncthreads();
        if (tid < 2) {
            float z0 = b2[0], z1 = b2[1];
            #pragma unroll
            for (int j = 0; j < 10; j++) {
                z0 = fmaf(zs[tid*10 + j], W2[j*2 + 0], z0);
                z1 = fmaf(zs[tid*10 + j], W2[j*2 + 1], z1);
            }
            z0 = sigm(z0); z1 = sigm(z1);
            float m = fmaxf(z0, z1);
            float e0 = expf(z0 - m), e1 = expf(z1 - m);
            float inv = 1.f/(e0 + e1);
            int bg = cta*2 + tid;
            out[((size_t)127*B_ + bg)*2 + 0] = e0*inv;
            out[((size_t)127*B_ + bg)*2 + 1] = e1*inv;
        }
    }
}

// ---------------------------------------------------------------------------
extern "C" void kernel_launch(void* const* d_in, const int* in_sizes, int n_in,
                              void* d_out, int out_size)
{
    const float* x     = (const float*)d_in[0];
    const float* dt    = (const float*)d_in[1];
    const float* mask  = (const float*)d_in[2];
    const float* tp    = (const float*)d_in[3];
    const float* xmean = (const float*)d_in[4];
    const float* h0    = (const float*)d_in[5];
    const float* c0    = (const float*)d_in[6];
    const float* wgx   = (const float*)d_in[7];
    const float* hgx   = (const float*)d_in[8];
    const float* wgh   = (const float*)d_in[9];
    const float* hgh   = (const float*)d_in[10];
    const float* wt    = (const float*)d_in[11];
    const float* ht    = (const float*)d_in[12];
    const float* Wih   = (const float*)d_in[13];
    const float* Whh   = (const float*)d_in[14];
    const float* bih   = (const float*)d_in[15];
    const float* bhh   = (const float*)d_in[16];
    const float* W1    = (const float*)d_in[17];
    const float* b1    = (const float*)d_in[18];
    const float* W2    = (const float*)d_in[19];
    const float* b2    = (const float*)d_in[20];
    float* out = (float*)d_out;

    const int PRE_SMEM  = (64 + 128) * LDK * 4;                 // 199,680 B
    const int LOOP_SMEM = (128 + 64) * LDK * 4 + 1024*4 + 128;  // 203,904 B
    static bool attr_done = false;
    if (!attr_done) {
        cudaFuncSetAttribute(k_g1,  cudaFuncAttributeMaxDynamicSharedMemorySize, PRE_SMEM);
        cudaFuncSetAttribute(k_g2,  cudaFuncAttributeMaxDynamicSharedMemorySize, PRE_SMEM);
        cudaFuncSetAttribute(k_g3,  cudaFuncAttributeMaxDynamicSharedMemorySize, PRE_SMEM);
        cudaFuncSetAttribute(k_loop, cudaFuncAttributeMaxDynamicSharedMemorySize, LOOP_SMEM);
        attr_done = true;
    }

    k_init<<<B_, H_>>>(h0);
    k_tr<<<768, 256>>>(wgx, wgh);
    k_g1<<<dim3(BT_/64, 2),  256, PRE_SMEM>>>(dt, hgx, x, mask, xmean, out);
    k_g2<<<dim3(BT_/64, 4),  256, PRE_SMEM>>>(dt, hgh);
    k_g3<<<dim3(BT_/64, 16), 256, PRE_SMEM>>>(out + XHAT_OFF, Wih, bih, bhh);
    k_loop<<<NCTA_LOOP, 256, LOOP_SMEM>>>(Whh, c0, tp, wt, ht, W1, b1, W2, b2, out);
}